// round 3
// baseline (speedup 1.0000x reference)
#include <cuda_runtime.h>
#include <cuda_fp16.h>

#define NN 50000
#define NG 500
#define EA 800000
#define EB 3200000
#define ET (EA + EB)
#define HID 128
#define OUTD 64
#define FULLM 0xffffffffu

// ---------------- device scratch (static, no allocation) ----------------
__device__ __half g_h[NN * OUTD];
__device__ float g_ssrc[NN];
__device__ float g_sdst[NN];
__device__ float g_x0[NN * HID];
__device__ float g_x1[NN * HID];
__device__ int   g_rowA[NN + 1];
__device__ int   g_colA[EA];
__device__ int   g_curA[NN];
__device__ int   g_rowB[NN + 1];
__device__ int   g_colB[EB];
__device__ int   g_curB[NN];

// ---------------- CSR build (4 edges / thread for atomic ILP) ------------
__global__ void count_both_k(const int* __restrict__ dA, const int* __restrict__ dB) {
    int i = (blockIdx.x * blockDim.x + threadIdx.x) * 4;
    if (i < EA) {
        int4 v = *(const int4*)(dA + i);
        atomicAdd(&g_curA[v.x], 1); atomicAdd(&g_curA[v.y], 1);
        atomicAdd(&g_curA[v.z], 1); atomicAdd(&g_curA[v.w], 1);
    } else if (i < ET) {
        int4 v = *(const int4*)(dB + (i - EA));
        atomicAdd(&g_curB[v.x], 1); atomicAdd(&g_curB[v.y], 1);
        atomicAdd(&g_curB[v.z], 1); atomicAdd(&g_curB[v.w], 1);
    }
}
// exclusive scan; block 0 -> set A, block 1 -> set B; also primes cur = row
__global__ void scan_both_k() {
    int* deg = blockIdx.x ? g_curB : g_curA;
    int* row = blockIdx.x ? g_rowB : g_rowA;
    __shared__ int part[1024];
    int t = threadIdx.x;
    const int C = (NN + 1023) / 1024;
    int b = t * C;
    int e = b + C; if (e > NN) e = NN;
    int s = 0;
    for (int i = b; i < e; ++i) s += deg[i];
    part[t] = s;
    __syncthreads();
    for (int off = 1; off < 1024; off <<= 1) {
        int v = (t >= off) ? part[t - off] : 0;
        __syncthreads();
        part[t] += v;
        __syncthreads();
    }
    int run = t ? part[t - 1] : 0;
    for (int i = b; i < e; ++i) {
        int d = deg[i];
        row[i] = run;
        deg[i] = run;   // cur = row start, for fill
        run += d;
    }
    if (t == 1023) row[NN] = part[1023];
}
__global__ void fill_both_k(const int* __restrict__ sA, const int* __restrict__ dA,
                            const int* __restrict__ sB, const int* __restrict__ dB) {
    int i = (blockIdx.x * blockDim.x + threadIdx.x) * 4;
    if (i < EA) {
        int4 d = *(const int4*)(dA + i);
        int4 s = *(const int4*)(sA + i);
        int p0 = atomicAdd(&g_curA[d.x], 1);
        int p1 = atomicAdd(&g_curA[d.y], 1);
        int p2 = atomicAdd(&g_curA[d.z], 1);
        int p3 = atomicAdd(&g_curA[d.w], 1);
        g_colA[p0] = s.x; g_colA[p1] = s.y; g_colA[p2] = s.z; g_colA[p3] = s.w;
    } else if (i < ET) {
        int k = i - EA;
        int4 d = *(const int4*)(dB + k);
        int4 s = *(const int4*)(sB + k);
        int p0 = atomicAdd(&g_curB[d.x], 1);
        int p1 = atomicAdd(&g_curB[d.y], 1);
        int p2 = atomicAdd(&g_curB[d.z], 1);
        int p3 = atomicAdd(&g_curB[d.w], 1);
        g_colB[p0] = s.x; g_colB[p1] = s.y; g_colB[p2] = s.z; g_colB[p3] = s.w;
    }
}

// --------- per-layer transform: h = x@W (fp16 out), s_src, s_dst ---------
// lane l owns output channels 2l and 2l+1
__global__ void feat_k(const float* __restrict__ x, const float* __restrict__ W,
                       const float* __restrict__ as_, const float* __restrict__ ad_) {
    __shared__ float Ws[HID * OUTD];
    for (int i = threadIdx.x; i < HID * OUTD; i += blockDim.x) Ws[i] = W[i];
    __syncthreads();
    int lane = threadIdx.x & 31;
    int wid = (blockIdx.x * blockDim.x + threadIdx.x) >> 5;
    int nw = (gridDim.x * blockDim.x) >> 5;
    float2 asv = ((const float2*)as_)[lane];
    float2 adv = ((const float2*)ad_)[lane];
    for (int n = wid; n < NN; n += nw) {
        const float* xr = x + n * HID;
        float xl0 = xr[lane], xl1 = xr[lane + 32], xl2 = xr[lane + 64], xl3 = xr[lane + 96];
        float h0 = 0.f, h1 = 0.f;
#pragma unroll
        for (int k = 0; k < 32; ++k) {
            float xv = __shfl_sync(FULLM, xl0, k);
            float2 wv = ((const float2*)Ws)[k * 32 + lane];
            h0 += xv * wv.x; h1 += xv * wv.y;
        }
#pragma unroll
        for (int k = 0; k < 32; ++k) {
            float xv = __shfl_sync(FULLM, xl1, k);
            float2 wv = ((const float2*)Ws)[(k + 32) * 32 + lane];
            h0 += xv * wv.x; h1 += xv * wv.y;
        }
#pragma unroll
        for (int k = 0; k < 32; ++k) {
            float xv = __shfl_sync(FULLM, xl2, k);
            float2 wv = ((const float2*)Ws)[(k + 64) * 32 + lane];
            h0 += xv * wv.x; h1 += xv * wv.y;
        }
#pragma unroll
        for (int k = 0; k < 32; ++k) {
            float xv = __shfl_sync(FULLM, xl3, k);
            float2 wv = ((const float2*)Ws)[(k + 96) * 32 + lane];
            h0 += xv * wv.x; h1 += xv * wv.y;
        }
        ((__half2*)g_h)[n * 32 + lane] = __floats2half2_rn(h0, h1);
        float s = h0 * asv.x + h1 * asv.y;
        float d = h0 * adv.x + h1 * adv.y;
#pragma unroll
        for (int o = 16; o; o >>= 1) {
            s += __shfl_xor_sync(FULLM, s, o);
            d += __shfl_xor_sync(FULLM, d, o);
        }
        if (lane == 0) { g_ssrc[n] = s; g_sdst[n] = d; }
    }
}

__device__ __forceinline__ float lrelu(float v) { return v > 0.f ? v : 0.2f * v; }

// ------------- GAT aggregation, warp per dst node, single pass -----------
// No max-stabilization: scores are O(1) by construction, exp(e)/sum(exp(e))
// is mathematically identical to the stabilized form.
__global__ void agg_k(const float* __restrict__ bias, float* __restrict__ xout) {
    int gw = (blockIdx.x * blockDim.x + threadIdx.x) >> 5;
    int lane = threadIdx.x & 31;
    if (gw >= 2 * NN) return;
    int isB = gw >= NN;
    int n = isB ? gw - NN : gw;
    const int* __restrict__ row = isB ? g_rowB : g_rowA;
    const int* __restrict__ col = isB ? g_colB : g_colA;
    int outOff = isB ? OUTD : 0;

    float sd = g_sdst[n];
    int b = row[n], e = row[n + 1];
    const __half2* __restrict__ h2 = (const __half2*)g_h;

    // self loop
    float ps = __expf(lrelu(g_ssrc[n] + sd));
    float2 hv = __half22float2(h2[n * 32 + lane]);
    float a0 = ps * hv.x, a1 = ps * hv.y;
    float c0 = 0.f, c1 = 0.f;
    float z = (lane == 0) ? ps : 0.f;

    int nfull = b + ((e - b) & ~31);
    for (int j0 = b; j0 < nfull; j0 += 32) {
        int se = col[j0 + lane];
        float pe = __expf(lrelu(__ldg(&g_ssrc[se]) + sd));
        z += pe;
#pragma unroll
        for (int t = 0; t < 32; t += 2) {
            float pt0 = __shfl_sync(FULLM, pe, t);
            int   st0 = __shfl_sync(FULLM, se, t);
            float pt1 = __shfl_sync(FULLM, pe, t + 1);
            int   st1 = __shfl_sync(FULLM, se, t + 1);
            float2 hh0 = __half22float2(__ldg(&h2[st0 * 32 + lane]));
            float2 hh1 = __half22float2(__ldg(&h2[st1 * 32 + lane]));
            a0 += pt0 * hh0.x; a1 += pt0 * hh0.y;
            c0 += pt1 * hh1.x; c1 += pt1 * hh1.y;
        }
    }
    // tail
    {
        int j = nfull + lane;
        float pe = 0.f; int se = 0;
        if (j < e) { se = col[j]; pe = __expf(lrelu(__ldg(&g_ssrc[se]) + sd)); }
        z += pe;
        int cnt = e - nfull;
        for (int t = 0; t < cnt; ++t) {
            float pt = __shfl_sync(FULLM, pe, t);
            int   st = __shfl_sync(FULLM, se, t);
            float2 hh = __half22float2(__ldg(&h2[st * 32 + lane]));
            a0 += pt * hh.x; a1 += pt * hh.y;
        }
    }
    a0 += c0; a1 += c1;
#pragma unroll
    for (int o = 16; o; o >>= 1) z += __shfl_xor_sync(FULLM, z, o);
    float inv = 1.f / z;
    float2 bv = ((const float2*)bias)[lane];
    float2 res;
    res.x = fmaxf(a0 * inv + bv.x, 0.f);
    res.y = fmaxf(a1 * inv + bv.y, 0.f);
    ((float2*)(xout + n * HID + outOff))[lane] = res;
}

// ------------- fused global add pool + final linear ----------------
__global__ void pool_final_k(const int* __restrict__ batch, const float* __restrict__ x,
                             const float* __restrict__ fw, const float* __restrict__ fb,
                             float* __restrict__ out) {
    int g = blockIdx.x;
    int t = threadIdx.x;  // 128 threads, one channel each
    __shared__ int bound[2];
    __shared__ float red[4];
    if (t < 2) {
        int target = g + t;
        int lo = 0, hi = NN;
        while (lo < hi) {
            int mid = (lo + hi) >> 1;
            if (batch[mid] < target) lo = mid + 1; else hi = mid;
        }
        bound[t] = lo;
    }
    __syncthreads();
    int lo = bound[0], hi = bound[1];
    float acc = 0.f;
    for (int n = lo; n < hi; ++n) acc += x[n * HID + t];
    acc *= fw[t];
#pragma unroll
    for (int o = 16; o; o >>= 1) acc += __shfl_xor_sync(FULLM, acc, o);
    if ((t & 31) == 0) red[t >> 5] = acc;
    __syncthreads();
    if (t == 0) out[g] = red[0] + red[1] + red[2] + red[3] + fb[0];
}

// ---------------- host launcher ----------------
extern "C" void kernel_launch(void* const* d_in, const int* in_sizes, int n_in,
                              void* d_out, int out_size) {
    const float* x       = (const float*)d_in[0];
    const int*   ei      = (const int*)d_in[1];
    const int*   di      = (const int*)d_in[2];
    const int*   batch   = (const int*)d_in[3];
    const float* lin_w   = (const float*)d_in[4];
    const float* att_src = (const float*)d_in[5];
    const float* att_dst = (const float*)d_in[6];
    const float* bias    = (const float*)d_in[7];
    const float* fw      = (const float*)d_in[8];
    const float* fb      = (const float*)d_in[9];
    float* out = (float*)d_out;

    void* p;
    cudaGetSymbolAddress(&p, g_x0);   float* x0 = (float*)p;
    cudaGetSymbolAddress(&p, g_x1);   float* x1 = (float*)p;
    cudaGetSymbolAddress(&p, g_curA); int* curA = (int*)p;
    cudaGetSymbolAddress(&p, g_curB); int* curB = (int*)p;

    const int* srcA = ei;  const int* dstA = ei + EA;
    const int* srcB = di;  const int* dstB = di + EB;

    // ---- build CSR (by dst) for both edge sets ----
    cudaMemsetAsync(curA, 0, NN * sizeof(int));
    cudaMemsetAsync(curB, 0, NN * sizeof(int));
    count_both_k<<<(ET / 4 + 255) / 256, 256>>>(dstA, dstB);
    scan_both_k<<<2, 1024>>>();
    fill_both_k<<<(ET / 4 + 255) / 256, 256>>>(srcA, dstA, srcB, dstB);

    // ---- 3 GAT layers ----
    const float* xin = x;
    float* xo = x0;
    for (int l = 0; l < 3; ++l) {
        feat_k<<<592, 256>>>(xin, lin_w + l * HID * OUTD,
                             att_src + l * OUTD, att_dst + l * OUTD);
        agg_k<<<(2 * NN * 32 + 255) / 256, 256>>>(bias + l * OUTD, xo);
        xin = xo;
        xo = (xo == x0) ? x1 : x0;
    }

    // ---- fused pooling + final projection ----
    pool_final_k<<<NG, 128>>>(batch, xin, fw, fb, out);
}

// round 4
// speedup vs baseline: 1.3378x; 1.3378x over previous
#include <cuda_runtime.h>
#include <cuda_fp16.h>

#define NN 50000
#define NG 500
#define EA 800000
#define EB 3200000
#define ET (EA + EB)
#define HID 128
#define OUTD 64
#define FULLM 0xffffffffu

// ---------------- device scratch (static, no allocation) ----------------
__device__ __half g_h[NN * OUTD];       // row-major [node][channel]
__device__ float g_ssrc[NN];
__device__ float g_sdst[NN];
__device__ float g_x0[NN * HID];
__device__ float g_x1[NN * HID];
__device__ int   g_rowA[NN + 1];
__device__ int   g_colA[EA];
__device__ int   g_curA[NN];
__device__ int   g_rowB[NN + 1];
__device__ int   g_colB[EB];
__device__ int   g_curB[NN];

// ---------------- CSR build (4 edges / thread for atomic ILP) ------------
__global__ void count_both_k(const int* __restrict__ dA, const int* __restrict__ dB) {
    int i = (blockIdx.x * blockDim.x + threadIdx.x) * 4;
    if (i < EA) {
        int4 v = *(const int4*)(dA + i);
        atomicAdd(&g_curA[v.x], 1); atomicAdd(&g_curA[v.y], 1);
        atomicAdd(&g_curA[v.z], 1); atomicAdd(&g_curA[v.w], 1);
    } else if (i < ET) {
        int4 v = *(const int4*)(dB + (i - EA));
        atomicAdd(&g_curB[v.x], 1); atomicAdd(&g_curB[v.y], 1);
        atomicAdd(&g_curB[v.z], 1); atomicAdd(&g_curB[v.w], 1);
    }
}
__global__ void scan_both_k() {
    int* deg = blockIdx.x ? g_curB : g_curA;
    int* row = blockIdx.x ? g_rowB : g_rowA;
    __shared__ int part[1024];
    int t = threadIdx.x;
    const int C = (NN + 1023) / 1024;
    int b = t * C;
    int e = b + C; if (e > NN) e = NN;
    int s = 0;
    for (int i = b; i < e; ++i) s += deg[i];
    part[t] = s;
    __syncthreads();
    for (int off = 1; off < 1024; off <<= 1) {
        int v = (t >= off) ? part[t - off] : 0;
        __syncthreads();
        part[t] += v;
        __syncthreads();
    }
    int run = t ? part[t - 1] : 0;
    for (int i = b; i < e; ++i) {
        int d = deg[i];
        row[i] = run;
        deg[i] = run;
        run += d;
    }
    if (t == 1023) row[NN] = part[1023];
}
__global__ void fill_both_k(const int* __restrict__ sA, const int* __restrict__ dA,
                            const int* __restrict__ sB, const int* __restrict__ dB) {
    int i = (blockIdx.x * blockDim.x + threadIdx.x) * 4;
    if (i < EA) {
        int4 d = *(const int4*)(dA + i);
        int4 s = *(const int4*)(sA + i);
        int p0 = atomicAdd(&g_curA[d.x], 1);
        int p1 = atomicAdd(&g_curA[d.y], 1);
        int p2 = atomicAdd(&g_curA[d.z], 1);
        int p3 = atomicAdd(&g_curA[d.w], 1);
        g_colA[p0] = s.x; g_colA[p1] = s.y; g_colA[p2] = s.z; g_colA[p3] = s.w;
    } else if (i < ET) {
        int k = i - EA;
        int4 d = *(const int4*)(dB + k);
        int4 s = *(const int4*)(sB + k);
        int p0 = atomicAdd(&g_curB[d.x], 1);
        int p1 = atomicAdd(&g_curB[d.y], 1);
        int p2 = atomicAdd(&g_curB[d.z], 1);
        int p3 = atomicAdd(&g_curB[d.w], 1);
        g_colB[p0] = s.x; g_colB[p1] = s.y; g_colB[p2] = s.z; g_colB[p3] = s.w;
    }
}

// --------- register-tiled SGEMM: h[node][c] = x[node][k] * W[k][c] -------
// block = 128 nodes x 64 cols, 256 threads (16 tx x 16 ty), thread tile 8x4
#define FT_NODES 128
#define FT_KC 16
__global__ __launch_bounds__(256) void feat_k(const float* __restrict__ x,
                                              const float* __restrict__ W) {
    __shared__ float ws[HID * OUTD];          // [k][c], 32KB
    __shared__ float xs[FT_KC][FT_NODES];     // [kk][node], 8KB
    int t = threadIdx.x;
    for (int i = t; i < HID * OUTD; i += 256) ws[i] = W[i];
    int nbase = blockIdx.x * FT_NODES;
    int tx = t & 15, ty = t >> 4;             // cols c0=tx*4, rows r0=ty*8
    int snode = t & 127, kseg = (t >> 7) * 8; // staging role
    int gnode = nbase + snode;
    float acc[8][4];
#pragma unroll
    for (int r = 0; r < 8; ++r)
#pragma unroll
        for (int c = 0; c < 4; ++c) acc[r][c] = 0.f;

    for (int k0 = 0; k0 < HID; k0 += FT_KC) {
        __syncthreads();
        float4 v0 = make_float4(0.f, 0.f, 0.f, 0.f), v1 = v0;
        if (gnode < NN) {
            const float4* xr = (const float4*)(x + gnode * HID + k0 + kseg);
            v0 = xr[0]; v1 = xr[1];
        }
        xs[kseg + 0][snode] = v0.x; xs[kseg + 1][snode] = v0.y;
        xs[kseg + 2][snode] = v0.z; xs[kseg + 3][snode] = v0.w;
        xs[kseg + 4][snode] = v1.x; xs[kseg + 5][snode] = v1.y;
        xs[kseg + 6][snode] = v1.z; xs[kseg + 7][snode] = v1.w;
        __syncthreads();
#pragma unroll
        for (int kk = 0; kk < FT_KC; ++kk) {
            float4 xa = *(const float4*)&xs[kk][ty * 8];
            float4 xb = *(const float4*)&xs[kk][ty * 8 + 4];
            float4 wv = *(const float4*)&ws[(k0 + kk) * OUTD + tx * 4];
            acc[0][0] += xa.x * wv.x; acc[0][1] += xa.x * wv.y; acc[0][2] += xa.x * wv.z; acc[0][3] += xa.x * wv.w;
            acc[1][0] += xa.y * wv.x; acc[1][1] += xa.y * wv.y; acc[1][2] += xa.y * wv.z; acc[1][3] += xa.y * wv.w;
            acc[2][0] += xa.z * wv.x; acc[2][1] += xa.z * wv.y; acc[2][2] += xa.z * wv.z; acc[2][3] += xa.z * wv.w;
            acc[3][0] += xa.w * wv.x; acc[3][1] += xa.w * wv.y; acc[3][2] += xa.w * wv.z; acc[3][3] += xa.w * wv.w;
            acc[4][0] += xb.x * wv.x; acc[4][1] += xb.x * wv.y; acc[4][2] += xb.x * wv.z; acc[4][3] += xb.x * wv.w;
            acc[5][0] += xb.y * wv.x; acc[5][1] += xb.y * wv.y; acc[5][2] += xb.y * wv.z; acc[5][3] += xb.y * wv.w;
            acc[6][0] += xb.z * wv.x; acc[6][1] += xb.z * wv.y; acc[6][2] += xb.z * wv.z; acc[6][3] += xb.z * wv.w;
            acc[7][0] += xb.w * wv.x; acc[7][1] += xb.w * wv.y; acc[7][2] += xb.w * wv.z; acc[7][3] += xb.w * wv.w;
        }
    }
#pragma unroll
    for (int r = 0; r < 8; ++r) {
        int node = nbase + ty * 8 + r;
        if (node < NN) {
            __half2 p0 = __floats2half2_rn(acc[r][0], acc[r][1]);
            __half2 p1 = __floats2half2_rn(acc[r][2], acc[r][3]);
            __half2* dst = (__half2*)(g_h + node * OUTD + tx * 4);
            dst[0] = p0; dst[1] = p1;
        }
    }
}

// --------- per-node attention scores from h ---------
__global__ void score_k(const float* __restrict__ as_, const float* __restrict__ ad_) {
    int gw = (blockIdx.x * blockDim.x + threadIdx.x) >> 5;
    int lane = threadIdx.x & 31;
    if (gw >= NN) return;
    float2 asv = ((const float2*)as_)[lane];
    float2 adv = ((const float2*)ad_)[lane];
    float2 hv = __half22float2(((const __half2*)g_h)[gw * 32 + lane]);
    float s = hv.x * asv.x + hv.y * asv.y;
    float d = hv.x * adv.x + hv.y * adv.y;
#pragma unroll
    for (int o = 16; o; o >>= 1) {
        s += __shfl_xor_sync(FULLM, s, o);
        d += __shfl_xor_sync(FULLM, d, o);
    }
    if (lane == 0) { g_ssrc[gw] = s; g_sdst[gw] = d; }
}

__device__ __forceinline__ float lrelu(float v) { return v > 0.f ? v : 0.2f * v; }

// ------------- GAT aggregation, warp per dst node, half-warp per edge ----
// No max-stabilization: scores are O(1), exp(e)/sum(exp(e)) is exact.
__global__ void agg_k(const float* __restrict__ bias, float* __restrict__ xout) {
    int gw = (blockIdx.x * blockDim.x + threadIdx.x) >> 5;
    int lane = threadIdx.x & 31;
    if (gw >= 2 * NN) return;
    int isB = gw >= NN;
    int n = isB ? gw - NN : gw;
    const int* __restrict__ row = isB ? g_rowB : g_rowA;
    const int* __restrict__ col = isB ? g_colB : g_colA;
    int outOff = isB ? OUTD : 0;

    float sd = g_sdst[n];
    int b = row[n], e = row[n + 1];
    const __half* __restrict__ hp = g_h + 4 * (lane & 15);  // 4 channels/lane
    int half_sel = lane & 16;

    float a0 = 0.f, a1 = 0.f, a2 = 0.f, a3 = 0.f;
    // self loop (low half-warp accumulates it)
    float ps = __expf(lrelu(g_ssrc[n] + sd));
    float z = (lane == 0) ? ps : 0.f;
    if (lane < 16) {
        uint2 raw = *(const uint2*)(hp + n * OUTD);
        float2 f0 = __half22float2(*(__half2*)&raw.x);
        float2 f1 = __half22float2(*(__half2*)&raw.y);
        a0 = ps * f0.x; a1 = ps * f0.y; a2 = ps * f1.x; a3 = ps * f1.y;
    }

    // prefetch first chunk
    int j = b + lane;
    int se = 0; float sv = 0.f;
    bool v = j < e;
    if (v) { se = col[j]; sv = __ldg(&g_ssrc[se]); }

    for (int j0 = b; j0 < e; j0 += 32) {
        float pe = v ? __expf(lrelu(sv + sd)) : 0.f;
        int seC = se;
        // prefetch next chunk (hides L2 latency behind broadcast chain)
        j += 32; v = j < e;
        if (v) { se = col[j]; sv = __ldg(&g_ssrc[se]); }
        z += pe;
        int cnt = e - j0;
        if (cnt >= 32) {
#pragma unroll
            for (int t = 0; t < 16; ++t) {
                int srcLane = t + half_sel;
                float pt = __shfl_sync(FULLM, pe, srcLane);
                int st = __shfl_sync(FULLM, seC, srcLane);
                uint2 raw = __ldg((const uint2*)(hp + st * OUTD));
                float2 f0 = __half22float2(*(__half2*)&raw.x);
                float2 f1 = __half22float2(*(__half2*)&raw.y);
                a0 += pt * f0.x; a1 += pt * f0.y; a2 += pt * f1.x; a3 += pt * f1.y;
            }
        } else {
            int iters = cnt < 16 ? cnt : 16;  // pe=0 padding covers the rest
            for (int t = 0; t < iters; ++t) {
                int srcLane = t + half_sel;
                float pt = __shfl_sync(FULLM, pe, srcLane);
                int st = __shfl_sync(FULLM, seC, srcLane);
                uint2 raw = __ldg((const uint2*)(hp + st * OUTD));
                float2 f0 = __half22float2(*(__half2*)&raw.x);
                float2 f1 = __half22float2(*(__half2*)&raw.y);
                a0 += pt * f0.x; a1 += pt * f0.y; a2 += pt * f1.x; a3 += pt * f1.y;
            }
        }
    }
#pragma unroll
    for (int o = 16; o; o >>= 1) z += __shfl_xor_sync(FULLM, z, o);
    // combine half-warp partials (lane l and l+16 own the same 4 channels)
    a0 += __shfl_xor_sync(FULLM, a0, 16);
    a1 += __shfl_xor_sync(FULLM, a1, 16);
    a2 += __shfl_xor_sync(FULLM, a2, 16);
    a3 += __shfl_xor_sync(FULLM, a3, 16);
    if (lane < 16) {
        float inv = 1.f / z;
        float4 bv = ((const float4*)bias)[lane];
        float4 res;
        res.x = fmaxf(a0 * inv + bv.x, 0.f);
        res.y = fmaxf(a1 * inv + bv.y, 0.f);
        res.z = fmaxf(a2 * inv + bv.z, 0.f);
        res.w = fmaxf(a3 * inv + bv.w, 0.f);
        *(float4*)(xout + n * HID + outOff + 4 * lane) = res;
    }
}

// ------------- fused global add pool + final linear ----------------
__global__ void pool_final_k(const int* __restrict__ batch, const float* __restrict__ x,
                             const float* __restrict__ fw, const float* __restrict__ fb,
                             float* __restrict__ out) {
    int g = blockIdx.x;
    int t = threadIdx.x;  // 128 threads, one channel each
    __shared__ int bound[2];
    __shared__ float red[4];
    if (t < 2) {
        int target = g + t;
        int lo = 0, hi = NN;
        while (lo < hi) {
            int mid = (lo + hi) >> 1;
            if (batch[mid] < target) lo = mid + 1; else hi = mid;
        }
        bound[t] = lo;
    }
    __syncthreads();
    int lo = bound[0], hi = bound[1];
    float acc = 0.f;
    for (int n = lo; n < hi; ++n) acc += x[n * HID + t];
    acc *= fw[t];
#pragma unroll
    for (int o = 16; o; o >>= 1) acc += __shfl_xor_sync(FULLM, acc, o);
    if ((t & 31) == 0) red[t >> 5] = acc;
    __syncthreads();
    if (t == 0) out[g] = red[0] + red[1] + red[2] + red[3] + fb[0];
}

// ---------------- host launcher ----------------
extern "C" void kernel_launch(void* const* d_in, const int* in_sizes, int n_in,
                              void* d_out, int out_size) {
    const float* x       = (const float*)d_in[0];
    const int*   ei      = (const int*)d_in[1];
    const int*   di      = (const int*)d_in[2];
    const int*   batch   = (const int*)d_in[3];
    const float* lin_w   = (const float*)d_in[4];
    const float* att_src = (const float*)d_in[5];
    const float* att_dst = (const float*)d_in[6];
    const float* bias    = (const float*)d_in[7];
    const float* fw      = (const float*)d_in[8];
    const float* fb      = (const float*)d_in[9];
    float* out = (float*)d_out;

    void* p;
    cudaGetSymbolAddress(&p, g_x0);   float* x0 = (float*)p;
    cudaGetSymbolAddress(&p, g_x1);   float* x1 = (float*)p;
    cudaGetSymbolAddress(&p, g_curA); int* curA = (int*)p;
    cudaGetSymbolAddress(&p, g_curB); int* curB = (int*)p;

    const int* srcA = ei;  const int* dstA = ei + EA;
    const int* srcB = di;  const int* dstB = di + EB;

    // ---- build CSR (by dst) for both edge sets ----
    cudaMemsetAsync(curA, 0, NN * sizeof(int));
    cudaMemsetAsync(curB, 0, NN * sizeof(int));
    count_both_k<<<(ET / 4 + 255) / 256, 256>>>(dstA, dstB);
    scan_both_k<<<2, 1024>>>();
    fill_both_k<<<(ET / 4 + 255) / 256, 256>>>(srcA, dstA, srcB, dstB);

    // ---- 3 GAT layers ----
    const float* xin = x;
    float* xo = x0;
    for (int l = 0; l < 3; ++l) {
        feat_k<<<(NN + FT_NODES - 1) / FT_NODES, 256>>>(xin, lin_w + l * HID * OUTD);
        score_k<<<(NN * 32 + 255) / 256, 256>>>(att_src + l * OUTD, att_dst + l * OUTD);
        agg_k<<<(2 * NN * 32 + 255) / 256, 256>>>(bias + l * OUTD, xo);
        xin = xo;
        xo = (xo == x0) ? x1 : x0;
    }

    // ---- fused pooling + final projection ----
    pool_final_k<<<NG, 128>>>(batch, xin, fw, fb, out);
}

// round 5
// speedup vs baseline: 1.4661x; 1.0958x over previous
#include <cuda_runtime.h>
#include <cuda_fp16.h>

#define NN 50000
#define NG 500
#define EA 800000
#define EB 3200000
#define ET (EA + EB)
#define HID 128
#define OUTD 64
#define FULLM 0xffffffffu

// ---------------- device scratch (static, no allocation) ----------------
__device__ __half g_h[NN * OUTD];       // row-major [node][channel]
__device__ float g_ssrc[NN];
__device__ float g_sdst[NN];
__device__ float g_x0[NN * HID];
__device__ float g_x1[NN * HID];
__device__ int   g_rowA[NN + 1];
__device__ int   g_colA[EA];
__device__ int   g_curA[NN];
__device__ int   g_rowB[NN + 1];
__device__ int   g_colB[EB];
__device__ int   g_curB[NN];

// ---------------- CSR build (4 edges / thread for atomic ILP) ------------
__global__ void count_both_k(const int* __restrict__ dA, const int* __restrict__ dB) {
    int i = (blockIdx.x * blockDim.x + threadIdx.x) * 4;
    if (i < EA) {
        int4 v = *(const int4*)(dA + i);
        atomicAdd(&g_curA[v.x], 1); atomicAdd(&g_curA[v.y], 1);
        atomicAdd(&g_curA[v.z], 1); atomicAdd(&g_curA[v.w], 1);
    } else if (i < ET) {
        int4 v = *(const int4*)(dB + (i - EA));
        atomicAdd(&g_curB[v.x], 1); atomicAdd(&g_curB[v.y], 1);
        atomicAdd(&g_curB[v.z], 1); atomicAdd(&g_curB[v.w], 1);
    }
}
__global__ void scan_both_k() {
    int* deg = blockIdx.x ? g_curB : g_curA;
    int* row = blockIdx.x ? g_rowB : g_rowA;
    __shared__ int part[1024];
    int t = threadIdx.x;
    const int C = (NN + 1023) / 1024;
    int b = t * C;
    int e = b + C; if (e > NN) e = NN;
    int s = 0;
    for (int i = b; i < e; ++i) s += deg[i];
    part[t] = s;
    __syncthreads();
    for (int off = 1; off < 1024; off <<= 1) {
        int v = (t >= off) ? part[t - off] : 0;
        __syncthreads();
        part[t] += v;
        __syncthreads();
    }
    int run = t ? part[t - 1] : 0;
    for (int i = b; i < e; ++i) {
        int d = deg[i];
        row[i] = run;
        deg[i] = run;
        run += d;
    }
    if (t == 1023) row[NN] = part[1023];
}
__global__ void fill_both_k(const int* __restrict__ sA, const int* __restrict__ dA,
                            const int* __restrict__ sB, const int* __restrict__ dB) {
    int i = (blockIdx.x * blockDim.x + threadIdx.x) * 4;
    if (i < EA) {
        int4 d = *(const int4*)(dA + i);
        int4 s = *(const int4*)(sA + i);
        int p0 = atomicAdd(&g_curA[d.x], 1);
        int p1 = atomicAdd(&g_curA[d.y], 1);
        int p2 = atomicAdd(&g_curA[d.z], 1);
        int p3 = atomicAdd(&g_curA[d.w], 1);
        g_colA[p0] = s.x; g_colA[p1] = s.y; g_colA[p2] = s.z; g_colA[p3] = s.w;
    } else if (i < ET) {
        int k = i - EA;
        int4 d = *(const int4*)(dB + k);
        int4 s = *(const int4*)(sB + k);
        int p0 = atomicAdd(&g_curB[d.x], 1);
        int p1 = atomicAdd(&g_curB[d.y], 1);
        int p2 = atomicAdd(&g_curB[d.z], 1);
        int p3 = atomicAdd(&g_curB[d.w], 1);
        g_colB[p0] = s.x; g_colB[p1] = s.y; g_colB[p2] = s.z; g_colB[p3] = s.w;
    }
}

// --------- register-tiled SGEMM + fused fp32 attention scores ------------
// block = 128 nodes x 64 cols, 256 threads (16 tx x 16 ty), thread tile 8x4
#define FT_NODES 128
#define FT_KC 16
__global__ __launch_bounds__(256) void feat_k(const float* __restrict__ x,
                                              const float* __restrict__ W,
                                              const float* __restrict__ as_,
                                              const float* __restrict__ ad_) {
    __shared__ float ws[HID * OUTD];          // [k][c], 32KB
    __shared__ float xs[FT_KC][FT_NODES];     // [kk][node], 8KB
    int t = threadIdx.x;
    for (int i = t; i < HID * OUTD; i += 256) ws[i] = W[i];
    int nbase = blockIdx.x * FT_NODES;
    int tx = t & 15, ty = t >> 4;             // cols c0=tx*4, rows r0=ty*8
    int snode = t & 127, kseg = (t >> 7) * 8; // staging role
    int gnode = nbase + snode;
    float acc[8][4];
#pragma unroll
    for (int r = 0; r < 8; ++r)
#pragma unroll
        for (int c = 0; c < 4; ++c) acc[r][c] = 0.f;

    for (int k0 = 0; k0 < HID; k0 += FT_KC) {
        __syncthreads();
        float4 v0 = make_float4(0.f, 0.f, 0.f, 0.f), v1 = v0;
        if (gnode < NN) {
            const float4* xr = (const float4*)(x + gnode * HID + k0 + kseg);
            v0 = xr[0]; v1 = xr[1];
        }
        xs[kseg + 0][snode] = v0.x; xs[kseg + 1][snode] = v0.y;
        xs[kseg + 2][snode] = v0.z; xs[kseg + 3][snode] = v0.w;
        xs[kseg + 4][snode] = v1.x; xs[kseg + 5][snode] = v1.y;
        xs[kseg + 6][snode] = v1.z; xs[kseg + 7][snode] = v1.w;
        __syncthreads();
#pragma unroll
        for (int kk = 0; kk < FT_KC; ++kk) {
            float4 xa = *(const float4*)&xs[kk][ty * 8];
            float4 xb = *(const float4*)&xs[kk][ty * 8 + 4];
            float4 wv = *(const float4*)&ws[(k0 + kk) * OUTD + tx * 4];
            acc[0][0] += xa.x * wv.x; acc[0][1] += xa.x * wv.y; acc[0][2] += xa.x * wv.z; acc[0][3] += xa.x * wv.w;
            acc[1][0] += xa.y * wv.x; acc[1][1] += xa.y * wv.y; acc[1][2] += xa.y * wv.z; acc[1][3] += xa.y * wv.w;
            acc[2][0] += xa.z * wv.x; acc[2][1] += xa.z * wv.y; acc[2][2] += xa.z * wv.z; acc[2][3] += xa.z * wv.w;
            acc[3][0] += xa.w * wv.x; acc[3][1] += xa.w * wv.y; acc[3][2] += xa.w * wv.z; acc[3][3] += xa.w * wv.w;
            acc[4][0] += xb.x * wv.x; acc[4][1] += xb.x * wv.y; acc[4][2] += xb.x * wv.z; acc[4][3] += xb.x * wv.w;
            acc[5][0] += xb.y * wv.x; acc[5][1] += xb.y * wv.y; acc[5][2] += xb.y * wv.z; acc[5][3] += xb.y * wv.w;
            acc[6][0] += xb.z * wv.x; acc[6][1] += xb.z * wv.y; acc[6][2] += xb.z * wv.z; acc[6][3] += xb.z * wv.w;
            acc[7][0] += xb.w * wv.x; acc[7][1] += xb.w * wv.y; acc[7][2] += xb.w * wv.z; acc[7][3] += xb.w * wv.w;
        }
    }
    // fp16 h writeback
#pragma unroll
    for (int r = 0; r < 8; ++r) {
        int node = nbase + ty * 8 + r;
        if (node < NN) {
            __half2 p0 = __floats2half2_rn(acc[r][0], acc[r][1]);
            __half2 p1 = __floats2half2_rn(acc[r][2], acc[r][3]);
            __half2* dst = (__half2*)(g_h + node * OUTD + tx * 4);
            dst[0] = p0; dst[1] = p1;
        }
    }
    // fused fp32 scores: reduce over the 16 tx lanes (low 4 lane bits)
    float4 asv = *(const float4*)(as_ + tx * 4);
    float4 adv = *(const float4*)(ad_ + tx * 4);
#pragma unroll
    for (int r = 0; r < 8; ++r) {
        float s = acc[r][0] * asv.x + acc[r][1] * asv.y + acc[r][2] * asv.z + acc[r][3] * asv.w;
        float d = acc[r][0] * adv.x + acc[r][1] * adv.y + acc[r][2] * adv.z + acc[r][3] * adv.w;
#pragma unroll
        for (int o = 8; o; o >>= 1) {
            s += __shfl_xor_sync(FULLM, s, o);
            d += __shfl_xor_sync(FULLM, d, o);
        }
        int node = nbase + ty * 8 + r;
        if (tx == 0 && node < NN) { g_ssrc[node] = s; g_sdst[node] = d; }
    }
}

__device__ __forceinline__ float lrelu(float v) { return v > 0.f ? v : 0.2f * v; }

// ------------- GAT aggregation, warp per dst node, half-warp per edge ----
// No max-stabilization: scores are O(1), exp(e)/sum(exp(e)) is exact.
// Every chunk uses the same fully-unrolled 16-iteration body; invalid lanes
// carry pe=0 / se=0 (zero contribution, in-bounds dummy load).
__global__ void agg_k(const float* __restrict__ bias, float* __restrict__ xout) {
    int gw = (blockIdx.x * blockDim.x + threadIdx.x) >> 5;
    int lane = threadIdx.x & 31;
    if (gw >= 2 * NN) return;
    int isB = gw >= NN;
    int n = isB ? gw - NN : gw;
    const int* __restrict__ row = isB ? g_rowB : g_rowA;
    const int* __restrict__ col = isB ? g_colB : g_colA;
    int outOff = isB ? OUTD : 0;

    float sd = g_sdst[n];
    int b = row[n], e = row[n + 1];
    const __half* __restrict__ hp = g_h + 4 * (lane & 15);  // 4 channels/lane
    int half_sel = lane & 16;

    float a0 = 0.f, a1 = 0.f, a2 = 0.f, a3 = 0.f;
    // self loop (low half-warp accumulates it)
    float ps = __expf(lrelu(g_ssrc[n] + sd));
    float z = (lane == 0) ? ps : 0.f;
    if (lane < 16) {
        uint2 raw = *(const uint2*)(hp + n * OUTD);
        float2 f0 = __half22float2(*(__half2*)&raw.x);
        float2 f1 = __half22float2(*(__half2*)&raw.y);
        a0 = ps * f0.x; a1 = ps * f0.y; a2 = ps * f1.x; a3 = ps * f1.y;
    }

    // prefetch first chunk
    int j = b + lane;
    int se = 0; float sv = 0.f;
    bool v = j < e;
    if (v) { se = col[j]; sv = __ldg(&g_ssrc[se]); }

    for (int j0 = b; j0 < e; j0 += 32) {
        float pe = v ? __expf(lrelu(sv + sd)) : 0.f;
        int seC = se;
        // prefetch next chunk (hides L2 latency behind broadcast chain)
        j += 32; v = j < e;
        se = 0; sv = 0.f;
        if (v) { se = col[j]; sv = __ldg(&g_ssrc[se]); }
        z += pe;
#pragma unroll
        for (int t = 0; t < 16; ++t) {
            int srcLane = t + half_sel;
            float pt = __shfl_sync(FULLM, pe, srcLane);
            int st = __shfl_sync(FULLM, seC, srcLane);
            uint2 raw = __ldg((const uint2*)(hp + st * OUTD));
            float2 f0 = __half22float2(*(__half2*)&raw.x);
            float2 f1 = __half22float2(*(__half2*)&raw.y);
            a0 += pt * f0.x; a1 += pt * f0.y; a2 += pt * f1.x; a3 += pt * f1.y;
        }
    }
#pragma unroll
    for (int o = 16; o; o >>= 1) z += __shfl_xor_sync(FULLM, z, o);
    // combine half-warp partials (lane l and l+16 own the same 4 channels)
    a0 += __shfl_xor_sync(FULLM, a0, 16);
    a1 += __shfl_xor_sync(FULLM, a1, 16);
    a2 += __shfl_xor_sync(FULLM, a2, 16);
    a3 += __shfl_xor_sync(FULLM, a3, 16);
    if (lane < 16) {
        float inv = 1.f / z;
        float4 bv = ((const float4*)bias)[lane];
        float4 res;
        res.x = fmaxf(a0 * inv + bv.x, 0.f);
        res.y = fmaxf(a1 * inv + bv.y, 0.f);
        res.z = fmaxf(a2 * inv + bv.z, 0.f);
        res.w = fmaxf(a3 * inv + bv.w, 0.f);
        *(float4*)(xout + n * HID + outOff + 4 * lane) = res;
    }
}

// ------------- fused global add pool + final linear ----------------
__global__ void pool_final_k(const int* __restrict__ batch, const float* __restrict__ x,
                             const float* __restrict__ fw, const float* __restrict__ fb,
                             float* __restrict__ out) {
    int g = blockIdx.x;
    int t = threadIdx.x;  // 128 threads, one channel each
    __shared__ int bound[2];
    __shared__ float red[4];
    if (t < 2) {
        int target = g + t;
        int lo = 0, hi = NN;
        while (lo < hi) {
            int mid = (lo + hi) >> 1;
            if (batch[mid] < target) lo = mid + 1; else hi = mid;
        }
        bound[t] = lo;
    }
    __syncthreads();
    int lo = bound[0], hi = bound[1];
    float acc = 0.f;
    for (int n = lo; n < hi; ++n) acc += x[n * HID + t];
    acc *= fw[t];
#pragma unroll
    for (int o = 16; o; o >>= 1) acc += __shfl_xor_sync(FULLM, acc, o);
    if ((t & 31) == 0) red[t >> 5] = acc;
    __syncthreads();
    if (t == 0) out[g] = red[0] + red[1] + red[2] + red[3] + fb[0];
}

// ---------------- host launcher ----------------
extern "C" void kernel_launch(void* const* d_in, const int* in_sizes, int n_in,
                              void* d_out, int out_size) {
    const float* x       = (const float*)d_in[0];
    const int*   ei      = (const int*)d_in[1];
    const int*   di      = (const int*)d_in[2];
    const int*   batch   = (const int*)d_in[3];
    const float* lin_w   = (const float*)d_in[4];
    const float* att_src = (const float*)d_in[5];
    const float* att_dst = (const float*)d_in[6];
    const float* bias    = (const float*)d_in[7];
    const float* fw      = (const float*)d_in[8];
    const float* fb      = (const float*)d_in[9];
    float* out = (float*)d_out;

    void* p;
    cudaGetSymbolAddress(&p, g_x0);   float* x0 = (float*)p;
    cudaGetSymbolAddress(&p, g_x1);   float* x1 = (float*)p;
    cudaGetSymbolAddress(&p, g_curA); int* curA = (int*)p;
    cudaGetSymbolAddress(&p, g_curB); int* curB = (int*)p;

    const int* srcA = ei;  const int* dstA = ei + EA;
    const int* srcB = di;  const int* dstB = di + EB;

    // ---- build CSR (by dst) for both edge sets ----
    cudaMemsetAsync(curA, 0, NN * sizeof(int));
    cudaMemsetAsync(curB, 0, NN * sizeof(int));
    count_both_k<<<(ET / 4 + 255) / 256, 256>>>(dstA, dstB);
    scan_both_k<<<2, 1024>>>();
    fill_both_k<<<(ET / 4 + 255) / 256, 256>>>(srcA, dstA, srcB, dstB);

    // ---- 3 GAT layers ----
    const float* xin = x;
    float* xo = x0;
    for (int l = 0; l < 3; ++l) {
        feat_k<<<(NN + FT_NODES - 1) / FT_NODES, 256>>>(xin, lin_w + l * HID * OUTD,
                                                        att_src + l * OUTD,
                                                        att_dst + l * OUTD);
        agg_k<<<(2 * NN * 32 + 255) / 256, 256>>>(bias + l * OUTD, xo);
        xin = xo;
        xo = (xo == x0) ? x1 : x0;
    }

    // ---- fused pooling + final projection ----
    pool_final_k<<<NG, 128>>>(batch, xin, fw, fb, out);
}